// round 17
// baseline (speedup 1.0000x reference)
#include <cuda_runtime.h>
#include <cstdint>
#include <math.h>

#define D_DIM   1024
#define T_DIM   50
#define STRIDEQ 10
#define NUM_POS 16
#define MAX_B   4096
#define MAX_KP  13108   /* ceil(131072/10) */
#define NWMAX   448     /* ceil(13108/32)=410, padded to chunk multiple */

typedef unsigned long long ull;

// ---- device scratch (static; no allocations allowed) ----
__device__ ulonglong2 g_q[MAX_KP];
__device__ ulonglong2 g_a[MAX_B];
__device__ int        g_sel[MAX_B * NUM_POS];
__device__ int        g_cnt[MAX_B];
__device__ float      g_per[MAX_B];
__device__ unsigned   g_counter;

// ------------------------------------------------------------------
// Kernel 1: pack labels (strided queue rows + anchors). Warp per row.
// ------------------------------------------------------------------
__global__ void prep_labels(const int* __restrict__ xlab,
                            const int* __restrict__ qlab,
                            int B, int Kp) {
    if (blockIdx.x == 0 && threadIdx.x == 0) g_counter = 0;
    int warp = (blockIdx.x * blockDim.x + threadIdx.x) >> 5;
    int lane = threadIdx.x & 31;
    if (warp >= Kp + B) return;

    const int* lp = (warp < Kp)
        ? qlab + (long long)warp * STRIDEQ * (T_DIM * 2)
        : xlab + (long long)(warp - Kp) * (T_DIM * 2);

    int2 va = ((const int2*)lp)[lane];
    int l0b = 0, l1b = 0;
    if (32 + lane < T_DIM) {
        int2 vb = ((const int2*)lp)[32 + lane];
        l0b = vb.x; l1b = vb.y;
    }
    unsigned b0lo = __ballot_sync(0xffffffffu, va.x != 0);
    unsigned b1lo = __ballot_sync(0xffffffffu, va.y != 0);
    unsigned b0hi = __ballot_sync(0xffffffffu, l0b != 0);
    unsigned b1hi = __ballot_sync(0xffffffffu, l1b != 0);
    if (lane == 0) {
        ull v0 = (ull)b0lo | ((ull)b0hi << 32);
        ull v1 = (ull)b1lo | ((ull)b1hi << 32);
        if (warp < Kp) g_q[warp]      = make_ulonglong2(v0, v1);
        else           g_a[warp - Kp] = make_ulonglong2(v0, v1);
    }
}

// ------------------------------------------------------------------
// Kernel 2: block-per-anchor select. Chunk=1024 (2 evals/thread,
// loads prefetched together), exit granularity 512 via two
// __syncthreads_count. Threshold table (bit-exact, validated).
// ------------------------------------------------------------------
__global__ void __launch_bounds__(512, 4)
select_block(int B, int Kp) {
    __shared__ unsigned s_words[NWMAX];
    __shared__ int      s_T[64];
    int b    = blockIdx.x;
    int tid  = threadIdx.x;
    int w    = tid >> 5;
    int lane = tid & 31;

    float c = 1.0f / (sqrtf(2.0f) + 1e-8f);
    if (tid < 64) {
        int nE = tid;
        int t;
        if ((float)nE >= 25.0f) t = 0;
        else {
            t = (int)((25.0f - (float)nE) / c) - 2;
            if (t < 0) t = 0;
            while ((float)nE + (float)t * c < 25.0f) t++;
        }
        s_T[tid] = t;
    }

    ulonglong2 av = g_a[b];
    ull a0 = av.x, a1 = av.y;
    ull da = a0 & a1, xa = a0 ^ a1, orA = a0 | a1;
    __syncthreads();

    int total    = 0;
    int scan_end = 0;
#pragma unroll 1
    for (int base = 0; base < Kp; base += 1024) {
        int k0 = base + tid;
        int k1 = base + 512 + tid;
        // both loads issued before use (MLP=2)
        ulonglong2 qv0 = g_q[k0 < Kp ? k0 : (Kp - 1)];
        ulonglong2 qv1 = g_q[k1 < Kp ? k1 : (Kp - 1)];
        bool p0 = false, p1 = false;
        if (k0 < Kp) {
            ull mE = ~(qv0.x ^ a0) & ~(qv0.y ^ a1) & orA;
            ull mc = (da & (qv0.x ^ qv0.y)) | (xa & (qv0.x & qv0.y));
            p0 = (__popcll(mc) >= s_T[__popcll(mE)]);
        }
        if (k1 < Kp) {
            ull mE = ~(qv1.x ^ a0) & ~(qv1.y ^ a1) & orA;
            ull mc = (da & (qv1.x ^ qv1.y)) | (xa & (qv1.x & qv1.y));
            p1 = (__popcll(mc) >= s_T[__popcll(mE)]);
        }
        unsigned m0 = __ballot_sync(0xffffffffu, p0);
        unsigned m1 = __ballot_sync(0xffffffffu, p1);
        if (lane == 0) {
            s_words[(base >> 5) + w]      = m0;
            s_words[(base >> 5) + 16 + w] = m1;
        }
        total += __syncthreads_count(p0);
        scan_end = (base + 512 < Kp) ? base + 512 : Kp;
        if (total >= NUM_POS) break;
        total += __syncthreads_count(p1);
        scan_end = (base + 1024 < Kp) ? base + 1024 : Kp;
        if (total >= NUM_POS) break;
    }

    // ---- ordered extraction of first <=16 hits (warp 0, validated) ----
    if (w == 0) {
        int nwords = (scan_end + 31) >> 5;
        int run = 0;
        for (int g = 0; g * 32 < nwords && run < NUM_POS; g++) {
            int wi = g * 32 + lane;
            unsigned word = (wi < nwords) ? s_words[wi] : 0u;
            int my = __popc(word);
            int pre = my;
#pragma unroll
            for (int o = 1; o < 32; o <<= 1) {
                int v = __shfl_up_sync(0xffffffffu, pre, o);
                if (lane >= o) pre += v;
            }
            int gtot = __shfl_sync(0xffffffffu, pre, 31);
            int rank = run + pre - my;
            while (word && rank < NUM_POS) {
                int bit = __ffs(word) - 1;
                word &= word - 1;
                g_sel[b * NUM_POS + rank++] = wi * 32 + bit;
            }
            run += gtot;
        }
        if (lane == 0) g_cnt[b] = (total < NUM_POS) ? total : NUM_POS;
    }
}

// ------------------------------------------------------------------
// Kernel 3: warp-per-anchor loss, k-pairs interleaved (16 LDG.128 in
// flight, 8 serial iterations). r-order accumulation preserved.
// ------------------------------------------------------------------
__global__ void __launch_bounds__(256)
loss_warp(const float* __restrict__ xq, const float* __restrict__ qf,
          float* __restrict__ out, int B) {
    __shared__ double s_red[256];
    __shared__ int    s_last;

    int tid  = threadIdx.x;
    int lane = tid & 31;
    int gw   = (blockIdx.x * 256 + tid) >> 5;   // global warp = anchor

    if (gw < B) {
        int b = gw;
        const float4* pa = (const float4*)(xq + (long long)b * D_DIM);
        float4 A[8];
#pragma unroll
        for (int i = 0; i < 8; i++) A[i] = pa[lane + i * 32];

        float qss = 0.f;
#pragma unroll
        for (int i = 0; i < 8; i++)
            qss += A[i].x * A[i].x + A[i].y * A[i].y
                 + A[i].z * A[i].z + A[i].w * A[i].w;
#pragma unroll
        for (int o = 16; o; o >>= 1) qss += __shfl_xor_sync(0xffffffffu, qss, o);
        float inv_q = 1.0f / (sqrtf(qss) + 1e-8f);

        int cnt = g_cnt[b];
        float lsum = 0.f;
#pragma unroll 1
        for (int r = 0; r < cnt; r += 2) {
            int kp0 = g_sel[b * NUM_POS + r];
            bool has1 = (r + 1 < cnt);
            int kp1 = has1 ? g_sel[b * NUM_POS + r + 1] : kp0;
            const float4* pk0 = (const float4*)(qf + (long long)kp0 * STRIDEQ * D_DIM);
            const float4* pk1 = (const float4*)(qf + (long long)kp1 * STRIDEQ * D_DIM);
            float d0 = 0.f, s0 = 0.f, d1 = 0.f, s1 = 0.f;
#pragma unroll
            for (int i = 0; i < 8; i++) {
                float4 k0 = pk0[lane + i * 32];
                float4 k1 = pk1[lane + i * 32];
                d0 += A[i].x * k0.x + A[i].y * k0.y + A[i].z * k0.z + A[i].w * k0.w;
                s0 += k0.x * k0.x + k0.y * k0.y + k0.z * k0.z + k0.w * k0.w;
                d1 += A[i].x * k1.x + A[i].y * k1.y + A[i].z * k1.z + A[i].w * k1.w;
                s1 += k1.x * k1.x + k1.y * k1.y + k1.z * k1.z + k1.w * k1.w;
            }
#pragma unroll
            for (int o = 16; o; o >>= 1) {
                d0 += __shfl_xor_sync(0xffffffffu, d0, o);
                s0 += __shfl_xor_sync(0xffffffffu, s0, o);
                d1 += __shfl_xor_sync(0xffffffffu, d1, o);
                s1 += __shfl_xor_sync(0xffffffffu, s1, o);
            }
            {
                float inv_k = 1.0f / (sqrtf(s0) + 1e-8f);
                float s = d0 * inv_q * inv_k * 2.0f;
                float z = -s;
                lsum += fmaxf(z, 0.f) + log1pf(expf(-fabsf(z)));
            }
            if (has1) {
                float inv_k = 1.0f / (sqrtf(s1) + 1e-8f);
                float s = d1 * inv_q * inv_k * 2.0f;
                float z = -s;
                lsum += fmaxf(z, 0.f) + log1pf(expf(-fabsf(z)));
            }
        }
        if (lane == 0)
            g_per[b] = (cnt > 0) ? (lsum / (float)cnt) : 0.f;
    }
    __syncthreads();

    if (tid == 0) {
        __threadfence();
        unsigned t = atomicAdd(&g_counter, 1u);
        s_last = (t == (unsigned)(gridDim.x - 1)) ? 1 : 0;
    }
    __syncthreads();

    // ---- last block: deterministic double-precision mean ----
    if (s_last) {
        double acc = 0.0;
        for (int i = tid; i < B; i += 256) acc += (double)g_per[i];
        s_red[tid] = acc;
        __syncthreads();
        for (int s = 128; s; s >>= 1) {
            if (tid < s) s_red[tid] += s_red[tid + s];
            __syncthreads();
        }
        if (tid == 0) out[0] = (float)(s_red[0] / (double)B);
    }
}

extern "C" void kernel_launch(void* const* d_in, const int* in_sizes, int n_in,
                              void* d_out, int out_size) {
    const float* xq   = (const float*)d_in[0];
    const int*   xlab = (const int*)  d_in[1];
    const float* qf   = (const float*)d_in[2];
    const int*   qlab = (const int*)  d_in[3];

    int B  = in_sizes[0] / D_DIM;                 // 4096
    int K  = in_sizes[2] / D_DIM;                 // 131072
    int Kp = (K + STRIDEQ - 1) / STRIDEQ;         // 13108

    int warps  = Kp + B;
    int blocks = (warps * 32 + 255) / 256;
    prep_labels <<<blocks, 256>>>(xlab, qlab, B, Kp);
    select_block<<<B, 512>>>(B, Kp);
    loss_warp   <<<(B * 32 + 255) / 256, 256>>>(xq, qf, (float*)d_out, B);
}